// round 11
// baseline (speedup 1.0000x reference)
#include <cuda_runtime.h>
#include <cuda_bf16.h>
#include <cstdint>

// Problem constants
#define BB 32
#define NS 262144
#define HH 256
#define WW 256
#define HWSZ (HH * WW)

constexpr int SEGS = 16;

// Per-(batch, segment) partial bounds: x=xmin, y=xmax, z=ymin, w=ymax.
__device__ float4 g_part[BB][SEGS];

// K1: grid = (SEGS, BB) = 512 blocks (single wave). Partial min/max + zero
// out-slice. Triggers immediately so the scatter kernel co-launches and
// overlaps its first payload loads.
__global__ __launch_bounds__(256) void minmax_kernel(const float* __restrict__ spatial,
                                                     float4* __restrict__ out4) {
    cudaTriggerProgrammaticLaunchCompletion();

    const int b = blockIdx.y;
    const int seg_elems = HWSZ / SEGS;                 // 4096 floats
    const float* base = spatial + (size_t)b * 2 * HWSZ + (size_t)blockIdx.x * seg_elems;
    const float4* vx = reinterpret_cast<const float4*>(base);
    const float4* vy = reinterpret_cast<const float4*>(base + HWSZ);

    float4 ax[4], ay[4];
    #pragma unroll
    for (int j = 0; j < 4; j++) ax[j] = vx[threadIdx.x + j * 256];
    #pragma unroll
    for (int j = 0; j < 4; j++) ay[j] = vy[threadIdx.x + j * 256];

    // Zero this block's slice of the output field (4096 floats / block).
    {
        const size_t blk = (size_t)b * SEGS + blockIdx.x;
        float4* oz = out4 + blk * 1024;
        const float4 z = make_float4(0.f, 0.f, 0.f, 0.f);
        #pragma unroll
        for (int j = 0; j < 4; j++) oz[threadIdx.x + j * 256] = z;
    }

    float xmn = 3.4e38f, xmx = -3.4e38f, ymn = 3.4e38f, ymx = -3.4e38f;
    #pragma unroll
    for (int j = 0; j < 4; j++) {
        xmn = fminf(xmn, fminf(fminf(ax[j].x, ax[j].y), fminf(ax[j].z, ax[j].w)));
        xmx = fmaxf(xmx, fmaxf(fmaxf(ax[j].x, ax[j].y), fmaxf(ax[j].z, ax[j].w)));
        ymn = fminf(ymn, fminf(fminf(ay[j].x, ay[j].y), fminf(ay[j].z, ay[j].w)));
        ymx = fmaxf(ymx, fmaxf(fmaxf(ay[j].x, ay[j].y), fmaxf(ay[j].z, ay[j].w)));
    }

    #pragma unroll
    for (int off = 16; off > 0; off >>= 1) {
        xmn = fminf(xmn, __shfl_xor_sync(0xFFFFFFFFu, xmn, off));
        xmx = fmaxf(xmx, __shfl_xor_sync(0xFFFFFFFFu, xmx, off));
        ymn = fminf(ymn, __shfl_xor_sync(0xFFFFFFFFu, ymn, off));
        ymx = fmaxf(ymx, __shfl_xor_sync(0xFFFFFFFFu, ymx, off));
    }

    __shared__ float4 s[8];
    const int wid = threadIdx.x >> 5;
    const int lid = threadIdx.x & 31;
    if (lid == 0) s[wid] = make_float4(xmn, xmx, ymn, ymx);
    __syncthreads();
    if (threadIdx.x == 0) {
        float4 r = s[0];
        #pragma unroll
        for (int w = 1; w < 8; w++) {
            r.x = fminf(r.x, s[w].x);
            r.y = fmaxf(r.y, s[w].y);
            r.z = fminf(r.z, s[w].z);
            r.w = fmaxf(r.w, s[w].w);
        }
        g_part[b][blockIdx.x] = r;
    }
}

// K2: persistent single-wave scatter. grid = SGRID blocks; each loops over
// (batch, chunk) tasks. Triggers at entry so mul_kernel co-launches early.
constexpr int TPB    = 256;
constexpr int IT     = 8;
constexpr int SGRID  = 608;                       // 4 blocks/SM * 152 = one wave
constexpr int CHUNKS = NS / (TPB * IT);           // 128 chunks per batch
constexpr int TASKS  = BB * CHUNKS;               // 4096

__global__ __launch_bounds__(TPB) void scatter_kernel(
    const float*  __restrict__ point_rates,
    const float2* __restrict__ coords,
    float*        __restrict__ out)
{
    cudaTriggerProgrammaticLaunchCompletion();

    const int tid = threadIdx.x;

    // Prefetch first task's payload (inputs only; independent of minmax).
    int t = blockIdx.x;
    float2 c[IT];
    float  rate[IT];
    {
        const int b  = t & (BB - 1);
        const int ch = t >> 5;
        const float2* cp  = coords + (size_t)ch * (TPB * IT);
        const float*  prp = point_rates + (size_t)b * NS + (size_t)ch * (TPB * IT);
        #pragma unroll
        for (int j = 0; j < IT; j++) c[j] = cp[tid + j * TPB];
        #pragma unroll
        for (int j = 0; j < IT; j++) rate[j] = prp[tid + j * TPB];
    }

    // Wait for minmax grid (bounds written, out zeroed).
    cudaGridDependencySynchronize();

    // Reduce all 32 batches' bounds into smem ONCE per block.
    __shared__ float4 sbnd[BB];
    {
        const int wid = tid >> 5;
        const int lid = tid & 31;
        for (int b = wid; b < BB; b += TPB / 32) {
            float xmn = 3.4e38f, xmx = -3.4e38f, ymn = 3.4e38f, ymx = -3.4e38f;
            if (lid < SEGS) {
                float4 p = g_part[b][lid];
                xmn = p.x; xmx = p.y; ymn = p.z; ymx = p.w;
            }
            #pragma unroll
            for (int off = 8; off > 0; off >>= 1) {
                xmn = fminf(xmn, __shfl_xor_sync(0xFFFFFFFFu, xmn, off));
                xmx = fmaxf(xmx, __shfl_xor_sync(0xFFFFFFFFu, xmx, off));
                ymn = fminf(ymn, __shfl_xor_sync(0xFFFFFFFFu, ymn, off));
                ymx = fmaxf(ymx, __shfl_xor_sync(0xFFFFFFFFu, ymx, off));
            }
            if (lid == 0) sbnd[b] = make_float4(xmn, xmx, ymn, ymx);
        }
    }
    __syncthreads();

    // Persistent task loop.
    while (true) {
        const int b = t & (BB - 1);
        float* ob = out + (size_t)b * HWSZ;
        const float4 B = sbnd[b];
        const float xmin = B.x, xmax = B.y, ymin = B.z, ymax = B.w;
        const float dx = __fsub_rn(xmax, xmin);
        const float dy = __fsub_rn(ymax, ymin);

        #pragma unroll
        for (int j = 0; j < IT; j++) {
            const bool iv = (c[j].x >= xmin) && (c[j].x <= xmax) &&
                            (c[j].y >= ymin) && (c[j].y <= ymax);
            // Match reference bit-exactly: strict IEEE rn sub/div/mul, then
            // round-half-even (== jnp.round) before clip.
            const float nx = __fdiv_rn(__fsub_rn(c[j].x, xmin), dx);
            const float ny = __fdiv_rn(__fsub_rn(c[j].y, ymin), dy);
            int px = __float2int_rn(__fmul_rn(nx, 255.0f));
            int py = __float2int_rn(__fmul_rn(ny, 255.0f));
            px = min(max(px, 0), WW - 1);
            py = min(max(py, 0), HH - 1);
            if (iv) {
                atomicAdd(&ob[py * WW + px], rate[j]);   // RED.ADD, no return
            }
        }

        t += SGRID;
        if (t >= TASKS) break;

        // Load next task's payload (REDG above is fire-and-forget).
        const int b2  = t & (BB - 1);
        const int ch2 = t >> 5;
        const float2* cp  = coords + (size_t)ch2 * (TPB * IT);
        const float*  prp = point_rates + (size_t)b2 * NS + (size_t)ch2 * (TPB * IT);
        #pragma unroll
        for (int j = 0; j < IT; j++) c[j] = cp[tid + j * TPB];
        #pragma unroll
        for (int j = 0; j < IT; j++) rate[j] = prp[tid + j * TPB];
    }
}

// K3: finalize (PDL). Co-launches during the scatter (single-wave trigger),
// prefetches gia under the atomic phase, then syncs and multiplies.
constexpr int MTPB = 256;
constexpr int MIT  = 4;
constexpr int MBLKS = (BB * HWSZ / 4) / (MTPB * MIT);   // 512 blocks

__global__ __launch_bounds__(MTPB) void mul_kernel(const float4* __restrict__ gia,
                                                   float4* __restrict__ out)
{
    const int i0 = blockIdx.x * MTPB + threadIdx.x;
    const int stride = MBLKS * MTPB;                     // 131072

    float4 g[MIT];
    #pragma unroll
    for (int j = 0; j < MIT; j++) g[j] = gia[i0 + j * stride];

    cudaGridDependencySynchronize();

    float4 o[MIT];
    #pragma unroll
    for (int j = 0; j < MIT; j++) o[j] = out[i0 + j * stride];

    #pragma unroll
    for (int j = 0; j < MIT; j++) {
        o[j].x = __fmul_rn(o[j].x, g[j].x);
        o[j].y = __fmul_rn(o[j].y, g[j].y);
        o[j].z = __fmul_rn(o[j].z, g[j].z);
        o[j].w = __fmul_rn(o[j].w, g[j].w);
        out[i0 + j * stride] = o[j];
    }
}

extern "C" void kernel_launch(void* const* d_in, const int* in_sizes, int n_in,
                              void* d_out, int out_size)
{
    const float*  point_rates = (const float*)d_in[0];   // (B, NS)
    const float*  spatial     = (const float*)d_in[1];   // (B, 2, H, W)
    const float*  gia         = (const float*)d_in[2];   // (B, H, W)
    const float2* coords      = (const float2*)d_in[3];  // (NS, 2)
    float* out = (float*)d_out;                          // (B, 1, H, W)

    cudaLaunchAttribute pdl[1];
    pdl[0].id = cudaLaunchAttributeProgrammaticStreamSerialization;
    pdl[0].val.programmaticStreamSerializationAllowed = 1;

    // K1: minmax partials + output zeroing (plain launch, triggers early)
    dim3 mg(SEGS, BB);
    minmax_kernel<<<mg, 256>>>(spatial, (float4*)out);

    // K2: persistent scatter, PDL (co-launches with K1, overlaps payload loads)
    {
        cudaLaunchConfig_t cfg = {};
        cfg.gridDim = dim3(SGRID);
        cfg.blockDim = dim3(TPB);
        cfg.stream = 0;
        cfg.attrs = pdl;
        cfg.numAttrs = 1;
        cudaLaunchKernelEx(&cfg, scatter_kernel, point_rates, coords, out);
    }

    // K3: mul, PDL (co-launches during K2's single wave; prefetches gia)
    {
        cudaLaunchConfig_t cfg = {};
        cfg.gridDim = dim3(MBLKS);
        cfg.blockDim = dim3(MTPB);
        cfg.stream = 0;
        cfg.attrs = pdl;
        cfg.numAttrs = 1;
        cudaLaunchKernelEx(&cfg, mul_kernel, (const float4*)gia, (float4*)out);
    }
}

// round 12
// speedup vs baseline: 1.3283x; 1.3283x over previous
#include <cuda_runtime.h>
#include <cuda_bf16.h>
#include <cstdint>

// Problem constants
#define BB 32
#define NS 262144
#define HH 256
#define WW 256
#define HWSZ (HH * WW)

constexpr int SEGS = 32;

// Per-(batch, segment) partial bounds: x = xmin, y = xmax, z = ymin, w = ymax.
__device__ float4 g_part[BB][SEGS];

// grid = (SEGS, BB) = 1024 blocks, block = 256.
// Computes partial min/max AND zeroes a slice of the output field.
__global__ __launch_bounds__(256) void minmax_kernel(const float* __restrict__ spatial,
                                                     float4* __restrict__ out4) {
    const int b = blockIdx.y;
    const int seg_elems = HWSZ / SEGS;                 // 2048 floats
    const float* base = spatial + (size_t)b * 2 * HWSZ + (size_t)blockIdx.x * seg_elems;
    const float4* vx = reinterpret_cast<const float4*>(base);
    const float4* vy = reinterpret_cast<const float4*>(base + HWSZ);

    float4 ax[2], ay[2];
    #pragma unroll
    for (int j = 0; j < 2; j++) ax[j] = vx[threadIdx.x + j * 256];
    #pragma unroll
    for (int j = 0; j < 2; j++) ay[j] = vy[threadIdx.x + j * 256];

    // Zero this block's slice of the output field (2048 floats / block).
    {
        const size_t blk = (size_t)b * SEGS + blockIdx.x;       // 0..1023
        float4* oz = out4 + blk * 512;
        const float4 z = make_float4(0.f, 0.f, 0.f, 0.f);
        #pragma unroll
        for (int j = 0; j < 2; j++) oz[threadIdx.x + j * 256] = z;
    }

    float xmn = 3.4e38f, xmx = -3.4e38f, ymn = 3.4e38f, ymx = -3.4e38f;
    #pragma unroll
    for (int j = 0; j < 2; j++) {
        xmn = fminf(xmn, fminf(fminf(ax[j].x, ax[j].y), fminf(ax[j].z, ax[j].w)));
        xmx = fmaxf(xmx, fmaxf(fmaxf(ax[j].x, ax[j].y), fmaxf(ax[j].z, ax[j].w)));
        ymn = fminf(ymn, fminf(fminf(ay[j].x, ay[j].y), fminf(ay[j].z, ay[j].w)));
        ymx = fmaxf(ymx, fmaxf(fmaxf(ay[j].x, ay[j].y), fmaxf(ay[j].z, ay[j].w)));
    }

    #pragma unroll
    for (int off = 16; off > 0; off >>= 1) {
        xmn = fminf(xmn, __shfl_xor_sync(0xFFFFFFFFu, xmn, off));
        xmx = fmaxf(xmx, __shfl_xor_sync(0xFFFFFFFFu, xmx, off));
        ymn = fminf(ymn, __shfl_xor_sync(0xFFFFFFFFu, ymn, off));
        ymx = fmaxf(ymx, __shfl_xor_sync(0xFFFFFFFFu, ymx, off));
    }

    __shared__ float4 s[8];
    const int wid = threadIdx.x >> 5;
    const int lid = threadIdx.x & 31;
    if (lid == 0) s[wid] = make_float4(xmn, xmx, ymn, ymx);
    __syncthreads();
    if (threadIdx.x == 0) {
        float4 r = s[0];
        #pragma unroll
        for (int w = 1; w < 8; w++) {
            r.x = fminf(r.x, s[w].x);
            r.y = fmaxf(r.y, s[w].y);
            r.z = fminf(r.z, s[w].z);
            r.w = fmaxf(r.w, s[w].w);
        }
        g_part[b][blockIdx.x] = r;
    }
}

// Scatter: launched with PDL. Payload loads (independent of minmax) are issued
// first; cudaGridDependencySynchronize() gates the bounds read + atomics.
constexpr int TPB = 256;
constexpr int IT  = 16;

__global__ __launch_bounds__(TPB) void scatter_kernel(
    const float*  __restrict__ point_rates,
    const float2* __restrict__ coords,
    float*        __restrict__ out)
{
    const int b = blockIdx.y;
    const float* pr = point_rates + (size_t)b * NS;
    float* ob = out + (size_t)b * HWSZ;

    const int base = blockIdx.x * (TPB * IT) + threadIdx.x;

    // Payload loads: inputs only — safe to issue while minmax still runs.
    float2 c[IT];
    float  rate[IT];
    #pragma unroll
    for (int j = 0; j < IT; j++) c[j] = coords[base + j * TPB];
    #pragma unroll
    for (int j = 0; j < IT; j++) rate[j] = pr[base + j * TPB];

    // Wait for minmax grid completion (bounds written, out zeroed).
    cudaGridDependencySynchronize();

    // Bounds prologue: one warp reduces the SEGS(=32) partials, one per lane.
    __shared__ float4 sb;
    if (threadIdx.x < 32) {
        float4 p = g_part[b][threadIdx.x];
        float xmn = p.x, xmx = p.y, ymn = p.z, ymx = p.w;
        #pragma unroll
        for (int off = 16; off > 0; off >>= 1) {
            xmn = fminf(xmn, __shfl_xor_sync(0xFFFFFFFFu, xmn, off));
            xmx = fmaxf(xmx, __shfl_xor_sync(0xFFFFFFFFu, xmx, off));
            ymn = fminf(ymn, __shfl_xor_sync(0xFFFFFFFFu, ymn, off));
            ymx = fmaxf(ymx, __shfl_xor_sync(0xFFFFFFFFu, ymx, off));
        }
        if (threadIdx.x == 0) sb = make_float4(xmn, xmx, ymn, ymx);
    }
    __syncthreads();

    const float xmin = sb.x, xmax = sb.y, ymin = sb.z, ymax = sb.w;
    const float dx = __fsub_rn(xmax, xmin);
    const float dy = __fsub_rn(ymax, ymin);

    #pragma unroll
    for (int j = 0; j < IT; j++) {
        const bool iv = (c[j].x >= xmin) && (c[j].x <= xmax) &&
                        (c[j].y >= ymin) && (c[j].y <= ymax);
        // Match reference bit-exactly: strict IEEE rn sub/div/mul, then
        // round-half-even (== jnp.round) before clip.
        const float nx = __fdiv_rn(__fsub_rn(c[j].x, xmin), dx);
        const float ny = __fdiv_rn(__fsub_rn(c[j].y, ymin), dy);
        int px = __float2int_rn(__fmul_rn(nx, 255.0f));
        int py = __float2int_rn(__fmul_rn(ny, 255.0f));
        px = min(max(px, 0), WW - 1);
        py = min(max(py, 0), HH - 1);
        if (iv) {
            atomicAdd(&ob[py * WW + px], rate[j]);   // RED.ADD, no return
        }
    }
}

// Streaming finalize (PDL): prefetch gia (4 loads in flight) before the
// grid-dep sync, then batch-load out, multiply, store.
constexpr int MTPB  = 256;
constexpr int MIT   = 4;
constexpr int MBLKS = (BB * HWSZ / 4) / (MTPB * MIT);   // 512 blocks

__global__ __launch_bounds__(MTPB) void mul_kernel(const float4* __restrict__ gia,
                                                   float4* __restrict__ out)
{
    const int i0 = blockIdx.x * MTPB + threadIdx.x;
    const int stride = MBLKS * MTPB;                     // 131072

    float4 g[MIT];
    #pragma unroll
    for (int j = 0; j < MIT; j++) g[j] = gia[i0 + j * stride];

    cudaGridDependencySynchronize();

    float4 o[MIT];
    #pragma unroll
    for (int j = 0; j < MIT; j++) o[j] = out[i0 + j * stride];

    #pragma unroll
    for (int j = 0; j < MIT; j++) {
        o[j].x = __fmul_rn(o[j].x, g[j].x);
        o[j].y = __fmul_rn(o[j].y, g[j].y);
        o[j].z = __fmul_rn(o[j].z, g[j].z);
        o[j].w = __fmul_rn(o[j].w, g[j].w);
        out[i0 + j * stride] = o[j];
    }
}

extern "C" void kernel_launch(void* const* d_in, const int* in_sizes, int n_in,
                              void* d_out, int out_size)
{
    const float*  point_rates = (const float*)d_in[0];   // (B, NS)
    const float*  spatial     = (const float*)d_in[1];   // (B, 2, H, W)
    const float*  gia         = (const float*)d_in[2];   // (B, H, W)
    const float2* coords      = (const float2*)d_in[3];  // (NS, 2)
    float* out = (float*)d_out;                          // (B, 1, H, W)

    // 1) minmax partials + output zeroing (plain launch)
    dim3 mg(SEGS, BB);
    minmax_kernel<<<mg, 256>>>(spatial, (float4*)out);

    cudaLaunchAttribute pdl[1];
    pdl[0].id = cudaLaunchAttributeProgrammaticStreamSerialization;
    pdl[0].val.programmaticStreamSerializationAllowed = 1;

    // 2) scatter with PDL: overlaps its payload loads with minmax drain
    {
        cudaLaunchConfig_t cfg = {};
        cfg.gridDim = dim3(NS / (TPB * IT), BB);
        cfg.blockDim = dim3(TPB);
        cfg.stream = 0;
        cfg.attrs = pdl;
        cfg.numAttrs = 1;
        cudaLaunchKernelEx(&cfg, scatter_kernel, point_rates, coords, out);
    }

    // 3) mul with PDL: overlaps gia prefetch with scatter drain
    {
        cudaLaunchConfig_t cfg = {};
        cfg.gridDim = dim3(MBLKS);
        cfg.blockDim = dim3(MTPB);
        cfg.stream = 0;
        cfg.attrs = pdl;
        cfg.numAttrs = 1;
        cudaLaunchKernelEx(&cfg, mul_kernel, (const float4*)gia, (float4*)out);
    }
}